// round 5
// baseline (speedup 1.0000x reference)
#include <cuda_runtime.h>
#include <cstdint>

#define BDIM 256
#define TDIM 1024
#define U    32
#define UNF  6
#define EPSV 1e-8f
#define SMAX 32
#define NRMAX 16
#define FULLM 0xffffffffu
#define NTICK (TDIM * (BDIM / 8))   // 32768 tickets, 8 batch-rows each

// 64 MB scratch: precomputed sensory (num, den) per (b,t,unit)
__device__ float2 g_sens[(size_t)BDIM * TDIM * U];
// per-timestep completion counters (32 tickets per t)
__device__ int g_cnt[TDIM];

// --- slotted recurrent synapse structures ---
// computing side: 4 slots per lane; lane l, slot s evaluates tanh(ca*v[csrc]-cb)
__device__ int   g_csrc[4 * U];
__device__ float g_ca[4 * U], g_cb[4 * U];
// gather side: round r, dst lane j fetches t[r&3] from lane g_ggl and applies weights
__device__ int   g_ggl[NRMAX * U];
__device__ float g_gwe[NRMAX * U], g_gwd[NRMAX * U];
__device__ float g_anum0[U], g_aden0[U];
__device__ int   g_na;            // max in-degree = #gather rounds

// per-column sparse sensory lists (tanh form)
__device__ int   g_ssrc[SMAX * U];
__device__ float g_sa[SMAX * U], g_sb[SMAX * U], g_sweh[SMAX * U], g_swdh[SMAX * U];
__device__ float g_snum0[U], g_sden0[U];
__device__ int   g_ns;

__device__ __forceinline__ float tanhf_a(float x) {
    float r; asm("tanh.approx.f32 %0, %1;" : "=f"(r) : "f"(x)); return r;
}
__device__ __forceinline__ float rcpf(float x) {
    float r; asm("rcp.approx.ftz.f32 %0, %1;" : "=f"(r) : "f"(x)); return r;
}
__device__ __forceinline__ int ld_acq(const int* p) {
    int v; asm volatile("ld.acquire.gpu.global.b32 %0, [%1];" : "=r"(v) : "l"(p)); return v;
}

// ---------------------------------------------------------------------------
// Setup. sigmoid(s(v-mu)) = 0.5 + 0.5*tanh(a*v - b), a = 0.5*s, b = 0.5*s*mu;
// constant halves fold into num0/den0.
// Thread 0 builds the slotted recurrent assignment (58 edges, trivial).
// Threads 32..63 build per-column sensory lists as before.
// ---------------------------------------------------------------------------
__global__ void __launch_bounds__(1024) setup_kernel(
    const int* __restrict__ spm, const float* __restrict__ wsyn,
    const float* __restrict__ mu, const float* __restrict__ sg,
    const float* __restrict__ er,
    const int* __restrict__ ssm, const float* __restrict__ sw,
    const float* __restrict__ smu, const float* __restrict__ ssg,
    const float* __restrict__ ser)
{
    __shared__ int   s_m[1024]; __shared__ float s_w[1024], s_mu[1024], s_sg[1024], s_er[1024];
    __shared__ int   t_m[1024]; __shared__ float t_w[1024], t_mu[1024], t_sg[1024], t_er[1024];
    int tid = threadIdx.x;
    g_cnt[tid] = 0;                            // reset readiness counters (every launch)
    s_m[tid] = spm[tid]; s_w[tid] = wsyn[tid]; s_mu[tid] = mu[tid];
    s_sg[tid] = sg[tid]; s_er[tid] = er[tid];
    t_m[tid] = ssm[tid]; t_w[tid] = sw[tid];  t_mu[tid] = smu[tid];
    t_sg[tid] = ssg[tid]; t_er[tid] = ser[tid];
    __syncthreads();

    if (tid == 0) {
        // zero computing cells
        for (int c = 0; c < 4 * U; c++) { g_csrc[c] = 0; g_ca[c] = 0.f; g_cb[c] = 0.f; }
        bool used[4][U];
        for (int s = 0; s < 4; s++) for (int l = 0; l < U; l++) used[s][l] = false;
        int maxdeg = 0;
        for (int j = 0; j < U; j++) {
            int k = 0;
            float n0 = 0.f, d0 = 0.f;
            for (int i = 0; i < U; i++) {
                int idx = i * U + j;
                if (s_m[idx] != 0 && k < NRMAX) {
                    int s = k & 3;
                    int l = 0;
                    for (int c = 0; c < U; c++) {
                        int cand = (j * 5 + k * 11 + c) & 31;
                        if (!used[s][cand]) { l = cand; break; }
                    }
                    used[s][l] = true;
                    float a   = 0.5f * s_sg[idx];
                    float weh = 0.5f * s_w[idx] * s_er[idx];
                    float wdh = 0.5f * s_w[idx];
                    g_csrc[s * U + l] = i;
                    g_ca[s * U + l]   = a;
                    g_cb[s * U + l]   = a * s_mu[idx];
                    g_ggl[k * U + j]  = l;
                    g_gwe[k * U + j]  = weh;
                    g_gwd[k * U + j]  = wdh;
                    n0 += weh; d0 += wdh;
                    k++;
                }
            }
            g_anum0[j] = n0; g_aden0[j] = d0;
            if (k > maxdeg) maxdeg = k;
            for (int kk = k; kk < NRMAX; kk++) {
                g_ggl[kk * U + j] = 0; g_gwe[kk * U + j] = 0.f; g_gwd[kk * U + j] = 0.f;
            }
        }
        g_na = maxdeg;
    } else if (tid >= 32 && tid < 64) {   // sensory lists, column j = tid-32
        int j = tid - 32, cnt = 0;
        float n0 = 0.f, d0 = 0.f;
        for (int i = 0; i < U; i++) {
            int idx = i * U + j;
            if (t_m[idx] != 0 && cnt < SMAX) {
                float a = 0.5f * t_sg[idx];
                float weh = 0.5f * t_w[idx] * t_er[idx];
                float wdh = 0.5f * t_w[idx];
                g_ssrc[cnt * U + j] = i;
                g_sa[cnt * U + j]   = a;
                g_sb[cnt * U + j]   = a * t_mu[idx];
                g_sweh[cnt * U + j] = weh;
                g_swdh[cnt * U + j] = wdh;
                n0 += weh; d0 += wdh;
                cnt++;
            }
        }
        for (int k = cnt; k < SMAX; k++) {
            g_ssrc[k * U + j] = 0;
            g_sa[k * U + j] = 0.f; g_sb[k * U + j] = 0.f;
            g_sweh[k * U + j] = 0.f; g_swdh[k * U + j] = 0.f;
        }
        g_snum0[j] = n0; g_sden0[j] = d0;
        int m = cnt;
        #pragma unroll
        for (int o = 16; o > 0; o >>= 1) m = max(m, __shfl_xor_sync(FULLM, m, o));
        if (j == 0) g_ns = m;
    }
}

// ---------------------------------------------------------------------------
// Fused producer/consumer kernel (unchanged structure from R4).
// ---------------------------------------------------------------------------
__device__ void sens_warp(
    int sw, int nw, int warp, int lane, float* smem,
    const float* __restrict__ x,
    const float* __restrict__ d1w, const float* __restrict__ d1b,
    const float* __restrict__ d2b,
    const float* __restrict__ iw,  const float* __restrict__ ib)
{
    float* sh_w2t = smem;                       // [32][132]
    float* sh_h1  = smem + 32 * 132 + warp * 1024;            // [8][128] per warp
    float* sh_in  = smem + 32 * 132 + 8 * 1024 + warp * 256;  // [8][32] per warp

    float wa[4], wb[4], bb[4];
    #pragma unroll
    for (int c = 0; c < 4; c++) {
        int k = c * 32 + lane;
        wa[c] = d1w[k]; wb[c] = d1w[128 + k]; bb[c] = d1b[k];
    }
    float dbl = d2b[lane], iwl = iw[lane], ibl = ib[lane];
    float n0 = g_snum0[lane], d0 = g_sden0[lane];
    int ns = g_ns;

    for (int q = sw; q < NTICK; q += nw) {
        int t  = q >> 5;
        int b0 = (q & 31) << 3;

        float2 xv = make_float2(0.f, 0.f);
        if (lane < 8) xv = ((const float2*)x)[(size_t)(b0 + lane) * TDIM + t];

        #pragma unroll
        for (int r = 0; r < 8; r++) {
            float x0 = __shfl_sync(FULLM, xv.x, r);
            float x1 = __shfl_sync(FULLM, xv.y, r);
            #pragma unroll
            for (int c = 0; c < 4; c++) {
                int k = c * 32 + lane;
                sh_h1[r * 128 + k] = fmaxf(fmaf(x0, wa[c], fmaf(x1, wb[c], bb[c])), 0.f);
            }
        }
        __syncwarp();

        float acc[8];
        #pragma unroll
        for (int r = 0; r < 8; r++) acc[r] = dbl;
        #pragma unroll 8
        for (int kq = 0; kq < 32; kq++) {
            float4 w4 = *(const float4*)&sh_w2t[lane * 132 + kq * 4];
            #pragma unroll
            for (int r = 0; r < 8; r++) {
                float4 h4 = *(const float4*)&sh_h1[r * 128 + kq * 4];
                acc[r] = fmaf(h4.x, w4.x, acc[r]);
                acc[r] = fmaf(h4.y, w4.y, acc[r]);
                acc[r] = fmaf(h4.z, w4.z, acc[r]);
                acc[r] = fmaf(h4.w, w4.w, acc[r]);
            }
        }
        #pragma unroll
        for (int r = 0; r < 8; r++) sh_in[r * 32 + lane] = fmaf(acc[r], iwl, ibl);
        __syncwarp();

        float num[8], den[8];
        #pragma unroll
        for (int r = 0; r < 8; r++) { num[r] = n0; den[r] = d0; }
        for (int k = 0; k < ns; k++) {
            int   src = g_ssrc[k * U + lane];
            float a   = g_sa[k * U + lane];
            float b   = g_sb[k * U + lane];
            float weh = g_sweh[k * U + lane];
            float wdh = g_swdh[k * U + lane];
            #pragma unroll
            for (int r = 0; r < 8; r++) {
                float tk = tanhf_a(fmaf(a, sh_in[r * 32 + src], -b));
                num[r] = fmaf(weh, tk, num[r]);
                den[r] = fmaf(wdh, tk, den[r]);
            }
        }
        #pragma unroll
        for (int r = 0; r < 8; r++)
            g_sens[((size_t)(b0 + r) * TDIM + t) * U + lane] = make_float2(num[r], den[r]);

        __threadfence();
        if (lane == 0) atomicAdd(&g_cnt[t], 1);
        __syncwarp();
    }
}

__device__ __forceinline__ void verify8(int base) {
    for (;;) {
        int ok = 1;
        #pragma unroll
        for (int i = 0; i < 8; i++)
            ok &= (ld_acq(&g_cnt[base + i]) == 32);
        if (ok) return;
        __nanosleep(200);
    }
}

// Slotted scan: 4 tanh per lane (fixed), NR cheap gather shfls.
template <int NR>
__device__ void scan_body(
    int lane, int batch,
    const float* __restrict__ gleak, const float* __restrict__ vleak,
    const float* __restrict__ cm,
    const float* __restrict__ ow, const float* __restrict__ ob,
    float* __restrict__ out)
{
    float gl   = gleak[lane];
    float cmt  = cm[lane] * (float)UNF;
    float gv   = gl * vleak[lane];
    float dcst = cmt + gl + EPSV + g_aden0[lane];
    float ncst = g_anum0[lane];

    // computing duties: 4 slots
    int cs[4]; float ca[4], cb[4];
    #pragma unroll
    for (int s = 0; s < 4; s++) {
        cs[s] = g_csrc[s * U + lane];
        ca[s] = g_ca[s * U + lane];
        cb[s] = g_cb[s * U + lane];
    }
    // gather duties: NR rounds
    int gla[NR]; float gwe[NR], gwd[NR];
    #pragma unroll
    for (int r = 0; r < NR; r++) {
        gla[r] = g_ggl[r * U + lane];
        gwe[r] = g_gwe[r * U + lane];
        gwd[r] = g_gwd[r * U + lane];
    }

    const float2* sp = g_sens + (size_t)batch * TDIM * U + lane;

    verify8(0);
    float2 sv = sp[0];
    float v = 0.f;

    for (int t = 0; t < TDIM; t++) {
        if ((t & 7) == 0 && t + 8 < TDIM) verify8(t + 8);
        int tn = (t + 1 < TDIM) ? (t + 1) : t;
        float2 nxt = sp[(size_t)tn * U];

        float nb = sv.x + ncst + gv;
        float db = sv.y + dcst;

        #pragma unroll
        for (int u = 0; u < UNF; u++) {
            // source-balanced tanh stage: exactly 4 MUFU per lane
            float tv[4];
            #pragma unroll
            for (int s = 0; s < 4; s++) {
                float vs = __shfl_sync(FULLM, v, cs[s]);
                tv[s] = tanhf_a(fmaf(ca[s], vs, -cb[s]));
            }
            // gather rounds: round r pulls slot (r&3) from computing lane
            float tk[NR];
            #pragma unroll
            for (int r = 0; r < NR; r++)
                tk[r] = __shfl_sync(FULLM, tv[r & 3], gla[r]);

            // den tree first -> rcp overlaps the num tree
            float dch[4];
            dch[0] = db; dch[1] = 0.f; dch[2] = 0.f; dch[3] = 0.f;
            #pragma unroll
            for (int r = 0; r < NR; r++)
                dch[r & 3] = fmaf(gwd[r], tk[r], dch[r & 3]);
            float den  = (dch[0] + dch[1]) + (dch[2] + dch[3]);
            float rden = rcpf(den);

            float nch[4];
            nch[0] = fmaf(cmt, v, nb); nch[1] = 0.f; nch[2] = 0.f; nch[3] = 0.f;
            #pragma unroll
            for (int r = 0; r < NR; r++)
                nch[r & 3] = fmaf(gwe[r], tk[r], nch[r & 3]);
            float num = (nch[0] + nch[1]) + (nch[2] + nch[3]);

            v = num * rden;
        }
        sv = nxt;
    }

    if (lane == 0) out[batch] = fmaf(v, ow[0], ob[0]);
}

__global__ void __launch_bounds__(256) fused_kernel(
    const float* __restrict__ x,
    const float* __restrict__ d1w, const float* __restrict__ d1b,
    const float* __restrict__ d2w, const float* __restrict__ d2b,
    const float* __restrict__ iw,  const float* __restrict__ ib,
    const float* __restrict__ gleak, const float* __restrict__ vleak,
    const float* __restrict__ cm,
    const float* __restrict__ ow, const float* __restrict__ ob,
    float* __restrict__ out)
{
    extern __shared__ float smem[];
    int tid = threadIdx.x, warp = tid >> 5, lane = tid & 31;

    // stage d2_w transposed [j][k] padded to 132
    for (int i = tid; i < 128 * 32; i += 256) {
        int k = i >> 5, j = i & 31;
        smem[j * 132 + k] = d2w[i];
    }
    __syncthreads();

    bool scanBlk = (blockIdx.x < 128);
    if (scanBlk && warp < 2) {
        int batch = blockIdx.x * 2 + warp;
        int na = g_na;
        if      (na <= 6)  scan_body<6 >(lane, batch, gleak, vleak, cm, ow, ob, out);
        else if (na <= 8)  scan_body<8 >(lane, batch, gleak, vleak, cm, ow, ob, out);
        else if (na <= 10) scan_body<10>(lane, batch, gleak, vleak, cm, ow, ob, out);
        else if (na <= 12) scan_body<12>(lane, batch, gleak, vleak, cm, ow, ob, out);
        else               scan_body<16>(lane, batch, gleak, vleak, cm, ow, ob, out);
    } else if (scanBlk) {
        if (warp == 4 || warp == 5) return;     // keep scan SMSPs clear
        int idx = (warp >= 6) ? (warp - 4) : (warp - 2);
        int sw = blockIdx.x * 4 + idx;
        int nw = 128 * 4 + (gridDim.x - 128) * 8;
        sens_warp(sw, nw, warp, lane, smem, x, d1w, d1b, d2b, iw, ib);
    } else {
        int sw = 128 * 4 + (blockIdx.x - 128) * 8 + warp;
        int nw = 128 * 4 + (gridDim.x - 128) * 8;
        sens_warp(sw, nw, warp, lane, smem, x, d1w, d1b, d2b, iw, ib);
    }
}

// ---------------------------------------------------------------------------
extern "C" void kernel_launch(void* const* d_in, const int* in_sizes, int n_in,
                              void* d_out, int out_size)
{
    const float* x    = (const float*)d_in[0];
    const float* d1w  = (const float*)d_in[1];
    const float* d1b  = (const float*)d_in[2];
    const float* d2w  = (const float*)d_in[3];
    const float* d2b  = (const float*)d_in[4];
    const float* iw   = (const float*)d_in[5];
    const float* ib   = (const float*)d_in[6];
    const float* ow   = (const float*)d_in[7];
    const float* ob   = (const float*)d_in[8];
    const float* gle  = (const float*)d_in[9];
    const float* vle  = (const float*)d_in[10];
    const float* cmv  = (const float*)d_in[11];
    const float* wsyn = (const float*)d_in[12];
    const float* muv  = (const float*)d_in[13];
    const float* sgv  = (const float*)d_in[14];
    const float* erv  = (const float*)d_in[15];
    const float* swv  = (const float*)d_in[16];
    const float* smuv = (const float*)d_in[17];
    const float* ssgv = (const float*)d_in[18];
    const float* serv = (const float*)d_in[19];
    const int*   spm  = (const int*)d_in[20];
    const int*   ssm  = (const int*)d_in[21];

    int nsm = 148;
    cudaDeviceGetAttribute(&nsm, cudaDevAttrMultiProcessorCount, 0);
    int blocks = (nsm > 128) ? nsm : 129;

    const int smemBytes = (32 * 132 + 8 * 1024 + 8 * 256) * sizeof(float);
    cudaFuncSetAttribute(fused_kernel, cudaFuncAttributeMaxDynamicSharedMemorySize, smemBytes);

    setup_kernel<<<1, 1024>>>(spm, wsyn, muv, sgv, erv, ssm, swv, smuv, ssgv, serv);
    fused_kernel<<<blocks, 256, smemBytes>>>(x, d1w, d1b, d2w, d2b, iw, ib,
                                             gle, vle, cmv, ow, ob, (float*)d_out);
}

// round 6
// speedup vs baseline: 1.0267x; 1.0267x over previous
#include <cuda_runtime.h>
#include <cstdint>

#define BDIM 256
#define TDIM 1024
#define U    32
#define UNF  6
#define EPSV 1e-8f
#define SMAX 32
#define CAPMAX 8
#define RMAX 4
#define FULLM 0xffffffffu
#define NTICK (TDIM * (BDIM / 8))   // 32768 tickets, 8 batch-rows each

// 64 MB scratch: precomputed sensory (num, den) per (b,t,unit)
__device__ float2 g_sens[(size_t)BDIM * TDIM * U];
// per-timestep completion counters (32 tickets per t)
__device__ int g_cnt[TDIM];

// --- owner/helper recurrent edge assignment ---
// computing cells: lane l evaluates up to CAP edges (tanh + weighted partials)
__device__ int   g_csrc[CAPMAX * U];
__device__ float g_ca[CAPMAX * U], g_cb[CAPMAX * U];
__device__ float g_cwe[CAPMAX * U], g_cwd[CAPMAX * U];
// gather rounds: dst lane j pulls partials from g_glane[r*U+j], masked by g_gmul
__device__ int   g_glane[RMAX * U];
__device__ float g_gmul[RMAX * U];
__device__ float g_anum0[U], g_aden0[U];   // folded 0.5-constant halves per dst
__device__ int   g_cap, g_rounds;

// per-column sparse sensory lists (tanh form)
__device__ int   g_ssrc[SMAX * U];
__device__ float g_sa[SMAX * U], g_sb[SMAX * U], g_sweh[SMAX * U], g_swdh[SMAX * U];
__device__ float g_snum0[U], g_sden0[U];
__device__ int   g_ns;

__device__ __forceinline__ float tanhf_a(float x) {
    float r; asm("tanh.approx.f32 %0, %1;" : "=f"(r) : "f"(x)); return r;
}
__device__ __forceinline__ float rcpf(float x) {
    float r; asm("rcp.approx.ftz.f32 %0, %1;" : "=f"(r) : "f"(x)); return r;
}
__device__ __forceinline__ int ld_acq(const int* p) {
    int v; asm volatile("ld.acquire.gpu.global.b32 %0, [%1];" : "=r"(v) : "l"(p)); return v;
}

// ---------------------------------------------------------------------------
// Setup. sigmoid(s(v-mu)) = 0.5 + 0.5*tanh(a*v - b); halves fold into num0/den0.
// Thread 0 builds the owner/helper assignment (58 edges; serial, runs once).
// ---------------------------------------------------------------------------
__global__ void __launch_bounds__(1024) setup_kernel(
    const int* __restrict__ spm, const float* __restrict__ wsyn,
    const float* __restrict__ mu, const float* __restrict__ sg,
    const float* __restrict__ er,
    const int* __restrict__ ssm, const float* __restrict__ sw,
    const float* __restrict__ smu, const float* __restrict__ ssg,
    const float* __restrict__ ser)
{
    __shared__ int   s_m[1024]; __shared__ float s_w[1024], s_mu[1024], s_sg[1024], s_er[1024];
    __shared__ int   t_m[1024]; __shared__ float t_w[1024], t_mu[1024], t_sg[1024], t_er[1024];
    int tid = threadIdx.x;
    g_cnt[tid] = 0;
    s_m[tid] = spm[tid]; s_w[tid] = wsyn[tid]; s_mu[tid] = mu[tid];
    s_sg[tid] = sg[tid]; s_er[tid] = er[tid];
    t_m[tid] = ssm[tid]; t_w[tid] = sw[tid];  t_mu[tid] = smu[tid];
    t_sg[tid] = ssg[tid]; t_er[tid] = ser[tid];
    __syncthreads();

    if (tid == 0) {
        int deg[U];
        for (int j = 0; j < U; j++) {
            int d = 0;
            for (int i = 0; i < U; i++) if (s_m[i * U + j] != 0) d++;
            deg[j] = d;
        }
        int nIdle = 0;
        for (int j = 0; j < U; j++) if (deg[j] == 0) nIdle++;

        // choose smallest CAP whose helper demand fits the idle lanes
        const int caps[4] = {2, 3, 4, 8};
        const int rlim[4] = {4, 3, 3, 4};
        int capSel = 8, rndSel = RMAX;
        for (int c = 0; c < 4; c++) {
            int CAP = caps[c], demand = 0, maxh = 0;
            for (int j = 0; j < U; j++) {
                int ex = deg[j] - CAP;
                int h = (ex > 0) ? (ex + CAP - 1) / CAP : 0;
                demand += h; if (h > maxh) maxh = h;
            }
            if (demand <= nIdle && 1 + maxh <= rlim[c]) {
                capSel = CAP; rndSel = 1 + maxh; break;
            }
        }
        g_cap = capSel; g_rounds = rndSel;

        // zero cells & rounds
        for (int c = 0; c < CAPMAX * U; c++) {
            g_csrc[c] = 0; g_ca[c] = 0.f; g_cb[c] = 0.f; g_cwe[c] = 0.f; g_cwd[c] = 0.f;
        }
        for (int r = 0; r < RMAX * U; r++) { g_glane[r] = 0; g_gmul[r] = 0.f; }

        bool isHelper[U];
        for (int l = 0; l < U; l++) isHelper[l] = false;
        int ecnt[U];
        for (int l = 0; l < U; l++) ecnt[l] = 0;

        for (int j = 0; j < U; j++) {
            // collect edges of column j
            int   src[U]; float ea[U], eb[U], ewe[U], ewd[U]; int d = 0;
            float n0 = 0.f, d0 = 0.f;
            for (int i = 0; i < U; i++) {
                int idx = i * U + j;
                if (s_m[idx] != 0) {
                    float a   = 0.5f * s_sg[idx];
                    float weh = 0.5f * s_w[idx] * s_er[idx];
                    float wdh = 0.5f * s_w[idx];
                    src[d] = i; ea[d] = a; eb[d] = a * s_mu[idx];
                    ewe[d] = weh; ewd[d] = wdh;
                    n0 += weh; d0 += wdh; d++;
                }
            }
            g_anum0[j] = n0; g_aden0[j] = d0;

            int pos = 0, r = 0;
            // owner chunk on lane j
            if (d > 0) {
                int take = (d < capSel) ? d : capSel;
                for (int e = 0; e < take; e++) {
                    g_csrc[e * U + j] = src[pos]; g_ca[e * U + j] = ea[pos];
                    g_cb[e * U + j] = eb[pos];   g_cwe[e * U + j] = ewe[pos];
                    g_cwd[e * U + j] = ewd[pos]; pos++;
                }
                ecnt[j] = take;
                g_glane[0 * U + j] = j; g_gmul[0 * U + j] = 1.f;
                r = 1;
            }
            // helper chunks
            while (pos < d) {
                int h = -1;
                for (int l = 0; l < U; l++)
                    if (deg[l] == 0 && !isHelper[l]) { h = l; break; }
                // feasibility guaranteed by CAP selection
                isHelper[h] = true;
                int take = (d - pos < capSel) ? (d - pos) : capSel;
                for (int e = 0; e < take; e++) {
                    g_csrc[e * U + h] = src[pos]; g_ca[e * U + h] = ea[pos];
                    g_cb[e * U + h] = eb[pos];   g_cwe[e * U + h] = ewe[pos];
                    g_cwd[e * U + h] = ewd[pos]; pos++;
                }
                ecnt[h] = take;
                g_glane[r * U + j] = h; g_gmul[r * U + j] = 1.f;
                r++;
            }
            // pad remaining rounds: self with zero mask
            for (; r < RMAX; r++) { g_glane[r * U + j] = j; g_gmul[r * U + j] = 0.f; }
        }
    } else if (tid >= 32 && tid < 64) {   // sensory lists, column j = tid-32
        int j = tid - 32, cnt = 0;
        float n0 = 0.f, d0 = 0.f;
        for (int i = 0; i < U; i++) {
            int idx = i * U + j;
            if (t_m[idx] != 0 && cnt < SMAX) {
                float a = 0.5f * t_sg[idx];
                float weh = 0.5f * t_w[idx] * t_er[idx];
                float wdh = 0.5f * t_w[idx];
                g_ssrc[cnt * U + j] = i;
                g_sa[cnt * U + j]   = a;
                g_sb[cnt * U + j]   = a * t_mu[idx];
                g_sweh[cnt * U + j] = weh;
                g_swdh[cnt * U + j] = wdh;
                n0 += weh; d0 += wdh;
                cnt++;
            }
        }
        for (int k = cnt; k < SMAX; k++) {
            g_ssrc[k * U + j] = 0;
            g_sa[k * U + j] = 0.f; g_sb[k * U + j] = 0.f;
            g_sweh[k * U + j] = 0.f; g_swdh[k * U + j] = 0.f;
        }
        g_snum0[j] = n0; g_sden0[j] = d0;
        int m = cnt;
        #pragma unroll
        for (int o = 16; o > 0; o >>= 1) m = max(m, __shfl_xor_sync(FULLM, m, o));
        if (j == 0) g_ns = m;
    }
}

// ---------------------------------------------------------------------------
// Fused producer/consumer kernel (structure identical to the 655us R4 version).
// ---------------------------------------------------------------------------
__device__ void sens_warp(
    int sw, int nw, int warp, int lane, float* smem,
    const float* __restrict__ x,
    const float* __restrict__ d1w, const float* __restrict__ d1b,
    const float* __restrict__ d2b,
    const float* __restrict__ iw,  const float* __restrict__ ib)
{
    float* sh_w2t = smem;                       // [32][132]
    float* sh_h1  = smem + 32 * 132 + warp * 1024;            // [8][128] per warp
    float* sh_in  = smem + 32 * 132 + 8 * 1024 + warp * 256;  // [8][32] per warp

    float wa[4], wb[4], bb[4];
    #pragma unroll
    for (int c = 0; c < 4; c++) {
        int k = c * 32 + lane;
        wa[c] = d1w[k]; wb[c] = d1w[128 + k]; bb[c] = d1b[k];
    }
    float dbl = d2b[lane], iwl = iw[lane], ibl = ib[lane];
    float n0 = g_snum0[lane], d0 = g_sden0[lane];
    int ns = g_ns;

    for (int q = sw; q < NTICK; q += nw) {
        int t  = q >> 5;
        int b0 = (q & 31) << 3;

        float2 xv = make_float2(0.f, 0.f);
        if (lane < 8) xv = ((const float2*)x)[(size_t)(b0 + lane) * TDIM + t];

        #pragma unroll
        for (int r = 0; r < 8; r++) {
            float x0 = __shfl_sync(FULLM, xv.x, r);
            float x1 = __shfl_sync(FULLM, xv.y, r);
            #pragma unroll
            for (int c = 0; c < 4; c++) {
                int k = c * 32 + lane;
                sh_h1[r * 128 + k] = fmaxf(fmaf(x0, wa[c], fmaf(x1, wb[c], bb[c])), 0.f);
            }
        }
        __syncwarp();

        float acc[8];
        #pragma unroll
        for (int r = 0; r < 8; r++) acc[r] = dbl;
        #pragma unroll 8
        for (int kq = 0; kq < 32; kq++) {
            float4 w4 = *(const float4*)&sh_w2t[lane * 132 + kq * 4];
            #pragma unroll
            for (int r = 0; r < 8; r++) {
                float4 h4 = *(const float4*)&sh_h1[r * 128 + kq * 4];
                acc[r] = fmaf(h4.x, w4.x, acc[r]);
                acc[r] = fmaf(h4.y, w4.y, acc[r]);
                acc[r] = fmaf(h4.z, w4.z, acc[r]);
                acc[r] = fmaf(h4.w, w4.w, acc[r]);
            }
        }
        #pragma unroll
        for (int r = 0; r < 8; r++) sh_in[r * 32 + lane] = fmaf(acc[r], iwl, ibl);
        __syncwarp();

        float num[8], den[8];
        #pragma unroll
        for (int r = 0; r < 8; r++) { num[r] = n0; den[r] = d0; }
        for (int k = 0; k < ns; k++) {
            int   src = g_ssrc[k * U + lane];
            float a   = g_sa[k * U + lane];
            float b   = g_sb[k * U + lane];
            float weh = g_sweh[k * U + lane];
            float wdh = g_swdh[k * U + lane];
            #pragma unroll
            for (int r = 0; r < 8; r++) {
                float tk = tanhf_a(fmaf(a, sh_in[r * 32 + src], -b));
                num[r] = fmaf(weh, tk, num[r]);
                den[r] = fmaf(wdh, tk, den[r]);
            }
        }
        #pragma unroll
        for (int r = 0; r < 8; r++)
            g_sens[((size_t)(b0 + r) * TDIM + t) * U + lane] = make_float2(num[r], den[r]);

        __threadfence();
        if (lane == 0) atomicAdd(&g_cnt[t], 1);
        __syncwarp();
    }
}

__device__ __forceinline__ void verify16(int base) {
    for (;;) {
        int ok = 1;
        #pragma unroll
        for (int i = 0; i < 16; i++)
            ok &= (ld_acq(&g_cnt[base + i]) == 32);
        if (ok) return;
        __nanosleep(200);
    }
}

// Owner/helper scan: CAP tanh per lane, RND masked gather rounds.
template <int CAP, int RND>
__device__ void scan_body(
    int lane, int batch,
    const float* __restrict__ gleak, const float* __restrict__ vleak,
    const float* __restrict__ cm,
    const float* __restrict__ ow, const float* __restrict__ ob,
    float* __restrict__ out)
{
    float gl   = gleak[lane];
    float cmt  = cm[lane] * (float)UNF;
    float gv   = gl * vleak[lane];
    float dcst = cmt + gl + EPSV + g_aden0[lane];
    float ncst = g_anum0[lane] + gv;

    int cs[CAP]; float ca[CAP], cb[CAP], cwe[CAP], cwd[CAP];
    #pragma unroll
    for (int e = 0; e < CAP; e++) {
        cs[e]  = g_csrc[e * U + lane];
        ca[e]  = g_ca[e * U + lane];
        cb[e]  = g_cb[e * U + lane];
        cwe[e] = g_cwe[e * U + lane];
        cwd[e] = g_cwd[e * U + lane];
    }
    int gl_[RND]; float gm[RND];
    #pragma unroll
    for (int r = 0; r < RND; r++) {
        gl_[r] = g_glane[r * U + lane];
        gm[r]  = g_gmul[r * U + lane];
    }

    const float2* sp = g_sens + (size_t)batch * TDIM * U + lane;

    verify16(0);
    float2 sv = sp[0];
    float v = 0.f;

    for (int t = 0; t < TDIM; t++) {
        if ((t & 15) == 0 && t + 16 < TDIM) verify16(t + 16);
        int tn = (t + 1 < TDIM) ? (t + 1) : t;
        float2 nxt = sp[(size_t)tn * U];

        float nb = sv.x + ncst;
        float db = sv.y + dcst;

        #pragma unroll
        for (int u = 0; u < UNF; u++) {
            // local edge evaluation (CAP tanh, short chains)
            float tv[CAP];
            #pragma unroll
            for (int e = 0; e < CAP; e++) {
                float vs = __shfl_sync(FULLM, v, cs[e]);
                tv[e] = tanhf_a(fmaf(ca[e], vs, -cb[e]));
            }
            float pn0 = 0.f, pn1 = 0.f, pd0 = 0.f, pd1 = 0.f;
            #pragma unroll
            for (int e = 0; e < CAP; e++) {
                if (e & 1) { pn1 = fmaf(cwe[e], tv[e], pn1); pd1 = fmaf(cwd[e], tv[e], pd1); }
                else       { pn0 = fmaf(cwe[e], tv[e], pn0); pd0 = fmaf(cwd[e], tv[e], pd0); }
            }
            float pn = pn0 + pn1, pd = pd0 + pd1;

            // masked gather of partials (1 + maxHelpers rounds)
            float na0 = fmaf(cmt, v, nb), na1 = 0.f;
            float da0 = db, da1 = 0.f;
            #pragma unroll
            for (int r = 0; r < RND; r++) {
                float spn = __shfl_sync(FULLM, pn, gl_[r]);
                float spd = __shfl_sync(FULLM, pd, gl_[r]);
                if (r & 1) { na1 = fmaf(gm[r], spn, na1); da1 = fmaf(gm[r], spd, da1); }
                else       { na0 = fmaf(gm[r], spn, na0); da0 = fmaf(gm[r], spd, da0); }
            }
            float den  = da0 + da1;
            float rden = rcpf(den);
            float num  = na0 + na1;
            v = num * rden;
        }
        sv = nxt;
    }

    if (lane == 0) out[batch] = fmaf(v, ow[0], ob[0]);
}

__global__ void __launch_bounds__(256) fused_kernel(
    const float* __restrict__ x,
    const float* __restrict__ d1w, const float* __restrict__ d1b,
    const float* __restrict__ d2w, const float* __restrict__ d2b,
    const float* __restrict__ iw,  const float* __restrict__ ib,
    const float* __restrict__ gleak, const float* __restrict__ vleak,
    const float* __restrict__ cm,
    const float* __restrict__ ow, const float* __restrict__ ob,
    float* __restrict__ out)
{
    extern __shared__ float smem[];
    int tid = threadIdx.x, warp = tid >> 5, lane = tid & 31;

    for (int i = tid; i < 128 * 32; i += 256) {
        int k = i >> 5, j = i & 31;
        smem[j * 132 + k] = d2w[i];
    }
    __syncthreads();

    bool scanBlk = (blockIdx.x < 128);
    if (scanBlk && warp < 2) {
        int batch = blockIdx.x * 2 + warp;
        int cap = g_cap, rnd = g_rounds;
        if (cap == 2) {
            if      (rnd <= 2) scan_body<2, 2>(lane, batch, gleak, vleak, cm, ow, ob, out);
            else if (rnd == 3) scan_body<2, 3>(lane, batch, gleak, vleak, cm, ow, ob, out);
            else               scan_body<2, 4>(lane, batch, gleak, vleak, cm, ow, ob, out);
        } else if (cap == 3) {
            if      (rnd <= 2) scan_body<3, 2>(lane, batch, gleak, vleak, cm, ow, ob, out);
            else               scan_body<3, 3>(lane, batch, gleak, vleak, cm, ow, ob, out);
        } else if (cap == 4) {
            if      (rnd <= 2) scan_body<4, 2>(lane, batch, gleak, vleak, cm, ow, ob, out);
            else               scan_body<4, 3>(lane, batch, gleak, vleak, cm, ow, ob, out);
        } else {
            scan_body<8, 4>(lane, batch, gleak, vleak, cm, ow, ob, out);
        }
    } else if (scanBlk) {
        if (warp == 4 || warp == 5) return;     // keep scan SMSPs clear
        int idx = (warp >= 6) ? (warp - 4) : (warp - 2);
        int sw = blockIdx.x * 4 + idx;
        int nw = 128 * 4 + (gridDim.x - 128) * 8;
        sens_warp(sw, nw, warp, lane, smem, x, d1w, d1b, d2b, iw, ib);
    } else {
        int sw = 128 * 4 + (blockIdx.x - 128) * 8 + warp;
        int nw = 128 * 4 + (gridDim.x - 128) * 8;
        sens_warp(sw, nw, warp, lane, smem, x, d1w, d1b, d2b, iw, ib);
    }
}

// ---------------------------------------------------------------------------
extern "C" void kernel_launch(void* const* d_in, const int* in_sizes, int n_in,
                              void* d_out, int out_size)
{
    const float* x    = (const float*)d_in[0];
    const float* d1w  = (const float*)d_in[1];
    const float* d1b  = (const float*)d_in[2];
    const float* d2w  = (const float*)d_in[3];
    const float* d2b  = (const float*)d_in[4];
    const float* iw   = (const float*)d_in[5];
    const float* ib   = (const float*)d_in[6];
    const float* ow   = (const float*)d_in[7];
    const float* ob   = (const float*)d_in[8];
    const float* gle  = (const float*)d_in[9];
    const float* vle  = (const float*)d_in[10];
    const float* cmv  = (const float*)d_in[11];
    const float* wsyn = (const float*)d_in[12];
    const float* muv  = (const float*)d_in[13];
    const float* sgv  = (const float*)d_in[14];
    const float* erv  = (const float*)d_in[15];
    const float* swv  = (const float*)d_in[16];
    const float* smuv = (const float*)d_in[17];
    const float* ssgv = (const float*)d_in[18];
    const float* serv = (const float*)d_in[19];
    const int*   spm  = (const int*)d_in[20];
    const int*   ssm  = (const int*)d_in[21];

    int nsm = 148;
    cudaDeviceGetAttribute(&nsm, cudaDevAttrMultiProcessorCount, 0);
    int blocks = (nsm > 128) ? nsm : 129;

    const int smemBytes = (32 * 132 + 8 * 1024 + 8 * 256) * sizeof(float);
    cudaFuncSetAttribute(fused_kernel, cudaFuncAttributeMaxDynamicSharedMemorySize, smemBytes);

    setup_kernel<<<1, 1024>>>(spm, wsyn, muv, sgv, erv, ssm, swv, smuv, ssgv, serv);
    fused_kernel<<<blocks, 256, smemBytes>>>(x, d1w, d1b, d2w, d2b, iw, ib,
                                             gle, vle, cmv, ow, ob, (float*)d_out);
}